// round 10
// baseline (speedup 1.0000x reference)
#include <cuda_runtime.h>
#include <cstdint>
#include <cstddef>

#define NN   50000
#define IND  1024
#define EE   100000
#define NR   40
#define NH   4
#define OD   200
#define HIDD 800
#define BB   8192

// ---- GEMM tiling (mma.sync tf32, sm_80-class features only) ----
#define BM   128
#define BN   160
#define BKK  32
#define NSTG (IND / BKK)        // 32
#define APAD 4
#define BPAD 8
#define ASTR (BKK + APAD)       // 36 words, conflict-free a-frag banks
#define BSTR (BN + BPAD)        // 168 words, conflict-free b-frag banks
#define A_WORDS (BM * ASTR)     // 4608
#define B_WORDS (BKK * BSTR)    // 5376
#define SMEM_WORDS (2 * (A_WORDS + B_WORDS))   // 19968 words = 79872 B

#define SCAN_BLKS ((NN + 255) / 256)           // 196

// ---------------- scratch (static device allocations, allowed) ----------------
static __device__ float g_h[(size_t)NN * HIDD];     // node features after GEMM  (160 MB)
static __device__ float g_out[(size_t)NN * HIDD];   // aggregated output (needed rows only)
static __device__ float g_Wtf[(size_t)IND * HIDD];  // tf32 pre-converted W       (3.3 MB)
static __device__ float g_sscore[NN * NH];
static __device__ float g_dscore[NN * NH];
static __device__ float g_relscore[NR * NH];
static __device__ float g_logits[EE * NH];
static __device__ float g_eexp[EE * NH];            // exp(logit - segmax)
static __device__ int   g_segmax[NN * NH];
static __device__ float g_denom[NN * NH];
static __device__ int   g_esrc[EE];
static __device__ int   g_edst[EE];
static __device__ int   g_etype[EE];
static __device__ int   g_deg[NN];
static __device__ int   g_need[NN];
static __device__ int   g_blocksum[SCAN_BLKS];
static __device__ int   g_blockoff[SCAN_BLKS];
static __device__ int   g_csr[NN + 1];
static __device__ int   g_fill[NN];
static __device__ int   g_eid[EE];
static __device__ int   g_sid[BB];
static __device__ int   g_rid[BB];
static __device__ int   g_did[BB];
static __device__ int   g_not64;   // 1 if index buffers are int32

// ---------------- helpers ----------------
__device__ __forceinline__ uint32_t smem_u32(const void* p) {
    uint32_t a;
    asm("{ .reg .u64 t; cvta.to.shared.u64 t, %1; cvt.u32.u64 %0, t; }" : "=r"(a) : "l"(p));
    return a;
}
__device__ __forceinline__ uint32_t f2tf32(float f) {
    uint32_t r;
    asm("cvt.rna.tf32.f32 %0, %1;" : "=r"(r) : "f"(f));
    return r;
}
__device__ __forceinline__ void mma_tf32(float* c, const uint32_t* a, const uint32_t* b) {
    asm volatile(
        "mma.sync.aligned.m16n8k8.row.col.f32.tf32.tf32.f32 "
        "{%0,%1,%2,%3}, {%4,%5,%6,%7}, {%8,%9}, {%0,%1,%2,%3};"
        : "+f"(c[0]), "+f"(c[1]), "+f"(c[2]), "+f"(c[3])
        : "r"(a[0]), "r"(a[1]), "r"(a[2]), "r"(a[3]), "r"(b[0]), "r"(b[1]));
}
#define CP_ASYNC16(dst, src) \
    asm volatile("cp.async.cg.shared.global [%0], [%1], 16;" :: "r"(dst), "l"(src))
#define CP_COMMIT()  asm volatile("cp.async.commit_group;" ::: "memory")
#define CP_WAIT(n)   asm volatile("cp.async.wait_group %0;" :: "n"(n) : "memory")

__device__ __forceinline__ int enc_f2i(float f) {
    int i = __float_as_int(f);
    return i >= 0 ? i : (i ^ 0x7fffffff);
}
__device__ __forceinline__ float dec_i2f(int k) {
    return __int_as_float(k >= 0 ? k : (k ^ 0x7fffffff));
}
__device__ __forceinline__ int fetch_idx(const void* p, long long i, int is64) {
    return is64 ? (int)((const long long*)p)[i] : ((const int*)p)[i];
}

// ---------------- init ----------------
__global__ void init_kernel() {
    int i = blockIdx.x * blockDim.x + threadIdx.x;
    if (i < NN * NH) { g_segmax[i] = INT_MIN; g_denom[i] = 0.0f; }
    if (i < NN) { g_deg[i] = 0; g_need[i] = 0; }
    if (i == 0) g_not64 = 0;
}

// ---------------- dtype detection ----------------
__global__ void detect_kernel(const void* edge_index) {
    int i = blockIdx.x * blockDim.x + threadIdx.x;
    if (i < EE) {
        int w = ((const int*)edge_index)[2 * i + 1];
        if (w != 0) g_not64 = 1;
    }
}

// ---------------- convert index arrays to int32 + degree histogram + need flags ----------------
__global__ void convert_kernel(const void* edge_index, const void* edge_type,
                               const void* src_ids, const void* rel_ids, const void* dst_ids) {
    int is64 = (g_not64 == 0);
    int i = blockIdx.x * blockDim.x + threadIdx.x;
    if (i < EE) {
        int s = fetch_idx(edge_index, i, is64);
        int d = fetch_idx(edge_index, (long long)EE + i, is64);
        g_esrc[i]  = s;
        g_edst[i]  = d;
        g_etype[i] = fetch_idx(edge_type, i, is64);
        atomicAdd(&g_deg[d], 1);
    }
    if (i < BB) {
        int s = fetch_idx(src_ids, i, is64);
        int d = fetch_idx(dst_ids, i, is64);
        g_sid[i] = s;
        g_rid[i] = fetch_idx(rel_ids, i, is64);
        g_did[i] = d;
        g_need[s] = 1;       // benign races: all write 1
        g_need[d] = 1;
    }
}

// ---------------- parallel 3-phase exclusive scan of degrees ----------------
__global__ void scan1_kernel() {
    __shared__ int sh[256];
    int t = threadIdx.x;
    int i = blockIdx.x * 256 + t;
    sh[t] = (i < NN) ? g_deg[i] : 0;
    __syncthreads();
#pragma unroll
    for (int off = 128; off; off >>= 1) {
        if (t < off) sh[t] += sh[t + off];
        __syncthreads();
    }
    if (t == 0) g_blocksum[blockIdx.x] = sh[0];
}

__global__ void scan2_kernel() {
    __shared__ int sh[256];
    int t = threadIdx.x;
    int v = (t < SCAN_BLKS) ? g_blocksum[t] : 0;
    sh[t] = v;
    __syncthreads();
#pragma unroll
    for (int off = 1; off < 256; off <<= 1) {
        int u = (t >= off) ? sh[t - off] : 0;
        __syncthreads();
        sh[t] += u;
        __syncthreads();
    }
    if (t < SCAN_BLKS) g_blockoff[t] = sh[t] - v;   // exclusive
}

__global__ void scan3_kernel() {
    __shared__ int sh[256];
    int t = threadIdx.x;
    int i = blockIdx.x * 256 + t;
    int v = (i < NN) ? g_deg[i] : 0;
    sh[t] = v;
    __syncthreads();
#pragma unroll
    for (int off = 1; off < 256; off <<= 1) {
        int u = (t >= off) ? sh[t - off] : 0;
        __syncthreads();
        sh[t] += u;
        __syncthreads();
    }
    if (i < NN) {
        int excl = g_blockoff[blockIdx.x] + sh[t] - v;
        g_csr[i]  = excl;
        g_fill[i] = excl;
    }
    if (i == 0) g_csr[NN] = EE;
}

// ---------------- scatter edge ids into CSR order ----------------
__global__ void scatter_kernel() {
    int e = blockIdx.x * blockDim.x + threadIdx.x;
    if (e >= EE) return;
    int pos = atomicAdd(&g_fill[g_edst[e]], 1);
    g_eid[pos] = e;
}

// ---------------- pre-convert W only (A converted inside GEMM prefetch) ----------------
__global__ void cvt_w_kernel(const float* __restrict__ W) {
    const int NW4 = IND * HIDD / 4;    // 204.8K
    int stride = gridDim.x * blockDim.x;
    for (int i = blockIdx.x * blockDim.x + threadIdx.x; i < NW4; i += stride) {
        float4 v = *(const float4*)(W + (size_t)i * 4);
        uint4 o = make_uint4(f2tf32(v.x), f2tf32(v.y), f2tf32(v.z), f2tf32(v.w));
        *(uint4*)(g_Wtf + (size_t)i * 4) = o;
    }
}

// ---------------- A loader: LDG fp32 ----------------
__device__ __forceinline__ void ldg_a(const float* __restrict__ A, int bm, int k0,
                                      int tid, float4* regs) {
#pragma unroll
    for (int i = 0; i < 4; i++) {
        int cid = tid + i * 256;
        int row = cid >> 3, kc = cid & 7;
        int g = bm + row; g = g < NN ? g : NN - 1;
        regs[i] = *(const float4*)(A + (size_t)g * IND + k0 + kc * 4);
    }
}
// ---------------- A storer: CVT + STS into padded smem ----------------
__device__ __forceinline__ void sts_a(float* sbuf, int tid, const float4* regs) {
#pragma unroll
    for (int i = 0; i < 4; i++) {
        int cid = tid + i * 256;
        int row = cid >> 3, kc = cid & 7;
        *(uint4*)(sbuf + row * ASTR + kc * 4) =
            make_uint4(f2tf32(regs[i].x), f2tf32(regs[i].y),
                       f2tf32(regs[i].z), f2tf32(regs[i].w));
    }
}
// ---------------- W prefetch via cp.async ----------------
__device__ __forceinline__ void prefetch_w(int bn, int k0, uint32_t sB, int tid) {
#pragma unroll
    for (int i = 0; i < 5; i++) {
        int cid = tid + i * 256;
        int row = cid / 40, nc = cid % 40;
        const float* src = g_Wtf + (size_t)(k0 + row) * HIDD + bn + nc * 4;
        uint32_t dst = sB + (uint32_t)(row * BSTR + nc * 4) * 4u;
        CP_ASYNC16(dst, src);
    }
}

// ---------------- TF32 mma.sync GEMM: g_h = cvt(A) @ W_tf32 ----------------
__global__ void __launch_bounds__(256, 2) mma_gemm_kernel(const float* __restrict__ A) {
    extern __shared__ float smf[];
    uint32_t sbase = smem_u32(smf);
    int tid = threadIdx.x, lane = tid & 31, w = tid >> 5;
    int bm = blockIdx.y * BM;
    int bn = blockIdx.x * BN;

    float* aBuf[2] = { smf, smf + A_WORDS + B_WORDS };
    uint32_t sB[2] = { sbase + (uint32_t)A_WORDS * 4u,
                       sbase + (uint32_t)(2 * A_WORDS + B_WORDS) * 4u };
    const uint32_t* fA[2] = { (const uint32_t*)smf,
                              (const uint32_t*)(smf + A_WORDS + B_WORDS) };
    const uint32_t* fB[2] = { (const uint32_t*)(smf + A_WORDS),
                              (const uint32_t*)(smf + 2 * A_WORDS + B_WORDS) };

    int wm = (w & 1) * 64;    // 2 warps along M
    int wn = (w >> 1) * 40;   // 4 warps along N
    int g4 = lane >> 2, t4 = lane & 3;

    float acc[4][5][4];
#pragma unroll
    for (int mt = 0; mt < 4; mt++)
#pragma unroll
        for (int nt = 0; nt < 5; nt++)
#pragma unroll
            for (int q = 0; q < 4; q++) acc[mt][nt][q] = 0.0f;

    // prologue: stage 0
    float4 areg[4];
    ldg_a(A, bm, 0, tid, areg);
    prefetch_w(bn, 0, sB[0], tid);
    CP_COMMIT();
    sts_a(aBuf[0], tid, areg);
    CP_WAIT(0);
    __syncthreads();

    for (int s = 0; s < NSTG; s++) {
        int b = s & 1;
        if (s + 1 < NSTG) {
            ldg_a(A, bm, (s + 1) * BKK, tid, areg);       // issue early, consumed post-MMA
            prefetch_w(bn, (s + 1) * BKK, sB[1 - b], tid);
            CP_COMMIT();
        }

        const uint32_t* as = fA[b];
        const uint32_t* bs = fB[b];
#pragma unroll
        for (int ks = 0; ks < 4; ks++) {
            uint32_t af[4][4], bf[5][2];
            int kk = ks * 8 + t4;
#pragma unroll
            for (int mt = 0; mt < 4; mt++) {
                int r = wm + mt * 16 + g4;
                af[mt][0] = as[r * ASTR + kk];
                af[mt][1] = as[(r + 8) * ASTR + kk];
                af[mt][2] = as[r * ASTR + kk + 4];
                af[mt][3] = as[(r + 8) * ASTR + kk + 4];
            }
#pragma unroll
            for (int nt = 0; nt < 5; nt++) {
                int col = wn + nt * 8 + g4;
                bf[nt][0] = bs[kk * BSTR + col];
                bf[nt][1] = bs[(kk + 4) * BSTR + col];
            }
#pragma unroll
            for (int mt = 0; mt < 4; mt++)
#pragma unroll
                for (int nt = 0; nt < 5; nt++)
                    mma_tf32(acc[mt][nt], af[mt], bf[nt]);
        }

        if (s + 1 < NSTG) {
            sts_a(aBuf[1 - b], tid, areg);   // other buffer: safe before barrier
            CP_WAIT(0);
        }
        __syncthreads();
    }

#pragma unroll
    for (int mt = 0; mt < 4; mt++) {
        int m0 = bm + wm + mt * 16 + g4;
#pragma unroll
        for (int nt = 0; nt < 5; nt++) {
            int n0 = bn + wn + nt * 8 + 2 * t4;
            if (m0 < NN)
                *(float2*)(g_h + (size_t)m0 * HIDD + n0) =
                    make_float2(acc[mt][nt][0], acc[mt][nt][1]);
            if (m0 + 8 < NN)
                *(float2*)(g_h + (size_t)(m0 + 8) * HIDD + n0) =
                    make_float2(acc[mt][nt][2], acc[mt][nt][3]);
        }
    }
}

// ---------------- per-node attention scores: warp per node ----------------
__global__ void node_scores_kernel(const float* __restrict__ a_src,
                                   const float* __restrict__ a_dst) {
    int warp = (blockIdx.x * blockDim.x + threadIdx.x) >> 5;
    int lane = threadIdx.x & 31;
    if (warp >= NN) return;
    const float* hrow = g_h + (size_t)warp * HIDD;
#pragma unroll
    for (int head = 0; head < NH; head++) {
        float ss = 0.f, dd = 0.f;
        for (int d = lane; d < OD; d += 32) {
            float hv = hrow[head * OD + d];
            ss = fmaf(hv, a_src[head * OD + d], ss);
            dd = fmaf(hv, a_dst[head * OD + d], dd);
        }
#pragma unroll
        for (int off = 16; off; off >>= 1) {
            ss += __shfl_xor_sync(0xffffffffu, ss, off);
            dd += __shfl_xor_sync(0xffffffffu, dd, off);
        }
        if (lane == 0) {
            g_sscore[warp * NH + head] = ss;
            g_dscore[warp * NH + head] = dd;
        }
    }
}

// ---------------- relation scores ----------------
__global__ void rel_scores_kernel(const float* __restrict__ rel_feat,
                                  const float* __restrict__ a_rel) {
    int t = threadIdx.x;
    if (t >= NR * NH) return;
    int r = t >> 2, hh = t & 3;
    float acc = 0.f;
    for (int d = 0; d < OD; d++)
        acc = fmaf(rel_feat[r * HIDD + hh * OD + d], a_rel[hh * OD + d], acc);
    g_relscore[t] = acc;
}

// ---------------- edge logits + leaky relu + segment max ----------------
__global__ void logits_kernel() {
    int t = blockIdx.x * blockDim.x + threadIdx.x;
    if (t >= EE * NH) return;
    int e = t >> 2, hh = t & 3;
    int s = g_esrc[e], d = g_edst[e], ty = g_etype[e];
    float l = g_sscore[s * NH + hh] + g_dscore[d * NH + hh] + g_relscore[ty * NH + hh];
    l = (l > 0.f) ? l : 0.2f * l;
    g_logits[t] = l;
    atomicMax(&g_segmax[d * NH + hh], enc_f2i(l));
}

// ---------------- exp + segment sum ----------------
__global__ void expsum_kernel() {
    int t = blockIdx.x * blockDim.x + threadIdx.x;
    if (t >= EE * NH) return;
    int e = t >> 2, hh = t & 3;
    int d = g_edst[e];
    float mx = dec_i2f(g_segmax[d * NH + hh]);
    float ev = __expf(g_logits[t] - mx);
    g_eexp[t] = ev;
    atomicAdd(&g_denom[d * NH + hh], ev);
}

// ---------------- CSR gather aggregate, needed dsts only ----------------
__global__ void __launch_bounds__(224) aggregate_csr_kernel() {
    int dst = blockIdx.x;
    if (!g_need[dst]) return;              // ~71% of blocks exit here
    int t = threadIdx.x;
    if (t >= 200) return;
    int head = t / 50;
    int beg = g_csr[dst], end = g_csr[dst + 1];
    float inv_den = (beg < end) ? __frcp_rn(g_denom[dst * NH + head]) : 0.0f;
    float4 acc = make_float4(0.f, 0.f, 0.f, 0.f);
    for (int p = beg; p < end; p++) {
        int e = g_eid[p];
        float a = g_eexp[e * NH + head] * inv_den;
        int src = g_esrc[e];
        float4 hv = *(const float4*)(g_h + (size_t)src * HIDD + t * 4);
        acc.x = fmaf(a, hv.x, acc.x);
        acc.y = fmaf(a, hv.y, acc.y);
        acc.z = fmaf(a, hv.z, acc.z);
        acc.w = fmaf(a, hv.w, acc.w);
    }
    *(float4*)(g_out + (size_t)dst * HIDD + t * 4) = acc;
}

// ---------------- DistMult scoring: warp per triple ----------------
__global__ void score_kernel(const float* __restrict__ bias,
                             const float* __restrict__ rel_emb,
                             float* __restrict__ out) {
    int warp = (blockIdx.x * blockDim.x + threadIdx.x) >> 5;
    int lane = threadIdx.x & 31;
    if (warp >= BB) return;
    int s = g_sid[warp], r = g_rid[warp], d = g_did[warp];
    const float* sv = g_out + (size_t)s * HIDD;
    const float* dv = g_out + (size_t)d * HIDD;
    const float* rv = rel_emb + (size_t)r * HIDD;
    float acc = 0.f;
    for (int j = lane; j < HIDD; j += 32)
        acc = fmaf((sv[j] + bias[j]) * rv[j], (dv[j] + bias[j]), acc);
#pragma unroll
    for (int off = 16; off; off >>= 1) acc += __shfl_xor_sync(0xffffffffu, acc, off);
    if (lane == 0) out[warp] = acc;
}

// ---------------- launch ----------------
extern "C" void kernel_launch(void* const* d_in, const int* in_sizes, int n_in,
                              void* d_out, int out_size) {
    const float* node_emb  = (const float*)d_in[0];
    const float* W         = (const float*)d_in[1];
    const float* bias      = (const float*)d_in[2];
    const float* a_src     = (const float*)d_in[3];
    const float* a_dst     = (const float*)d_in[4];
    const float* a_rel     = (const float*)d_in[5];
    const float* rel_feat  = (const float*)d_in[6];
    const float* rel_emb   = (const float*)d_in[7];
    const void*  edge_index = d_in[8];
    const void*  edge_type  = d_in[9];
    const void*  src_ids    = d_in[10];
    const void*  rel_ids    = d_in[11];
    const void*  dst_ids    = d_in[12];
    float* out = (float*)d_out;

    static bool attr_set = false;
    if (!attr_set) {
        cudaFuncSetAttribute(mma_gemm_kernel,
                             cudaFuncAttributeMaxDynamicSharedMemorySize,
                             SMEM_WORDS * 4);
        attr_set = true;
    }

    init_kernel<<<(NN * NH + 255) / 256, 256>>>();
    detect_kernel<<<(EE + 255) / 256, 256>>>(edge_index);
    convert_kernel<<<(EE + 255) / 256, 256>>>(edge_index, edge_type, src_ids, rel_ids, dst_ids);
    scan1_kernel<<<SCAN_BLKS, 256>>>();
    scan2_kernel<<<1, 256>>>();
    scan3_kernel<<<SCAN_BLKS, 256>>>();
    scatter_kernel<<<(EE + 255) / 256, 256>>>();

    cvt_w_kernel<<<512, 256>>>(W);

    dim3 ggrid(HIDD / BN, (NN + BM - 1) / BM);   // (5, 391)
    mma_gemm_kernel<<<ggrid, 256, SMEM_WORDS * 4>>>(node_emb);

    node_scores_kernel<<<(NN * 32 + 255) / 256, 256>>>(a_src, a_dst);
    rel_scores_kernel<<<1, 256>>>(rel_feat, a_rel);
    logits_kernel<<<(EE * NH + 255) / 256, 256>>>();
    expsum_kernel<<<(EE * NH + 255) / 256, 256>>>();
    aggregate_csr_kernel<<<NN, 224>>>();
    score_kernel<<<(BB * 32 + 255) / 256, 256>>>(bias, rel_emb, out);
}

// round 11
// speedup vs baseline: 1.8107x; 1.8107x over previous
#include <cuda_runtime.h>
#include <cstdint>
#include <cstddef>

#define NN   50000
#define IND  1024
#define EE   100000
#define NR   40
#define NH   4
#define OD   200
#define HIDD 800
#define BB   8192

// ---- GEMM tiling (mma.sync tf32, sm_80-class features only) ----
#define BM   128
#define BN   160
#define BKK  32
#define NSTG (IND / BKK)        // 32
#define APAD 4
#define BPAD 8
#define ASTR (BKK + APAD)       // 36 words, conflict-free a-frag banks
#define BSTR (BN + BPAD)        // 168 words, conflict-free b-frag banks
#define A_WORDS (BM * ASTR)     // 4608
#define B_WORDS (BKK * BSTR)    // 5376
#define SMEM_WORDS (2 * (A_WORDS + B_WORDS))   // 19968 words = 79872 B

#define SCAN_BLKS ((NN + 255) / 256)           // 196

// ---------------- scratch (static device allocations, allowed) ----------------
static __device__ float g_h[(size_t)NN * HIDD];     // node features after GEMM  (160 MB)
static __device__ float g_out[(size_t)NN * HIDD];   // aggregated output (needed rows only)
static __device__ float g_Atf[(size_t)NN * IND];    // tf32 pre-converted A       (205 MB)
static __device__ float g_Wtf[(size_t)IND * HIDD];  // tf32 pre-converted W       (3.3 MB)
static __device__ float g_sscore[NN * NH];
static __device__ float g_dscore[NN * NH];
static __device__ float g_relscore[NR * NH];
static __device__ float g_logits[EE * NH];
static __device__ float g_eexp[EE * NH];            // exp(logit - segmax)
static __device__ int   g_segmax[NN * NH];
static __device__ float g_denom[NN * NH];
static __device__ int   g_esrc[EE];
static __device__ int   g_edst[EE];
static __device__ int   g_etype[EE];
static __device__ int   g_deg[NN];
static __device__ int   g_need[NN];
static __device__ int   g_blocksum[SCAN_BLKS];
static __device__ int   g_blockoff[SCAN_BLKS];
static __device__ int   g_csr[NN + 1];
static __device__ int   g_fill[NN];
static __device__ int   g_eid[EE];
static __device__ int   g_sid[BB];
static __device__ int   g_rid[BB];
static __device__ int   g_did[BB];
static __device__ int   g_not64;   // 1 if index buffers are int32

// ---------------- helpers ----------------
__device__ __forceinline__ uint32_t smem_u32(const void* p) {
    uint32_t a;
    asm("{ .reg .u64 t; cvta.to.shared.u64 t, %1; cvt.u32.u64 %0, t; }" : "=r"(a) : "l"(p));
    return a;
}
__device__ __forceinline__ uint32_t f2tf32(float f) {
    uint32_t r;
    asm("cvt.rna.tf32.f32 %0, %1;" : "=r"(r) : "f"(f));
    return r;
}
__device__ __forceinline__ void mma_tf32(float* c, const uint32_t* a, const uint32_t* b) {
    asm volatile(
        "mma.sync.aligned.m16n8k8.row.col.f32.tf32.tf32.f32 "
        "{%0,%1,%2,%3}, {%4,%5,%6,%7}, {%8,%9}, {%0,%1,%2,%3};"
        : "+f"(c[0]), "+f"(c[1]), "+f"(c[2]), "+f"(c[3])
        : "r"(a[0]), "r"(a[1]), "r"(a[2]), "r"(a[3]), "r"(b[0]), "r"(b[1]));
}
#define CP_ASYNC16(dst, src) \
    asm volatile("cp.async.cg.shared.global [%0], [%1], 16;" :: "r"(dst), "l"(src))
#define CP_COMMIT()  asm volatile("cp.async.commit_group;" ::: "memory")
#define CP_WAIT(n)   asm volatile("cp.async.wait_group %0;" :: "n"(n) : "memory")

__device__ __forceinline__ int enc_f2i(float f) {
    int i = __float_as_int(f);
    return i >= 0 ? i : (i ^ 0x7fffffff);
}
__device__ __forceinline__ float dec_i2f(int k) {
    return __int_as_float(k >= 0 ? k : (k ^ 0x7fffffff));
}
__device__ __forceinline__ int fetch_idx(const void* p, long long i, int is64) {
    return is64 ? (int)((const long long*)p)[i] : ((const int*)p)[i];
}

// ---------------- init ----------------
__global__ void init_kernel() {
    int i = blockIdx.x * blockDim.x + threadIdx.x;
    if (i < NN * NH) { g_segmax[i] = INT_MIN; g_denom[i] = 0.0f; }
    if (i < NN) { g_deg[i] = 0; g_need[i] = 0; }
    if (i == 0) g_not64 = 0;
}

// ---------------- dtype detection ----------------
__global__ void detect_kernel(const void* edge_index) {
    int i = blockIdx.x * blockDim.x + threadIdx.x;
    if (i < EE) {
        int w = ((const int*)edge_index)[2 * i + 1];
        if (w != 0) g_not64 = 1;
    }
}

// ---------------- convert index arrays to int32 + degree histogram + need flags ----------------
__global__ void convert_kernel(const void* edge_index, const void* edge_type,
                               const void* src_ids, const void* rel_ids, const void* dst_ids) {
    int is64 = (g_not64 == 0);
    int i = blockIdx.x * blockDim.x + threadIdx.x;
    if (i < EE) {
        int s = fetch_idx(edge_index, i, is64);
        int d = fetch_idx(edge_index, (long long)EE + i, is64);
        g_esrc[i]  = s;
        g_edst[i]  = d;
        g_etype[i] = fetch_idx(edge_type, i, is64);
        atomicAdd(&g_deg[d], 1);
    }
    if (i < BB) {
        int s = fetch_idx(src_ids, i, is64);
        int d = fetch_idx(dst_ids, i, is64);
        g_sid[i] = s;
        g_rid[i] = fetch_idx(rel_ids, i, is64);
        g_did[i] = d;
        g_need[s] = 1;       // benign races: all write 1
        g_need[d] = 1;
    }
}

// ---------------- parallel 3-phase exclusive scan of degrees ----------------
__global__ void scan1_kernel() {
    __shared__ int sh[256];
    int t = threadIdx.x;
    int i = blockIdx.x * 256 + t;
    sh[t] = (i < NN) ? g_deg[i] : 0;
    __syncthreads();
#pragma unroll
    for (int off = 128; off; off >>= 1) {
        if (t < off) sh[t] += sh[t + off];
        __syncthreads();
    }
    if (t == 0) g_blocksum[blockIdx.x] = sh[0];
}

__global__ void scan2_kernel() {
    __shared__ int sh[256];
    int t = threadIdx.x;
    int v = (t < SCAN_BLKS) ? g_blocksum[t] : 0;
    sh[t] = v;
    __syncthreads();
#pragma unroll
    for (int off = 1; off < 256; off <<= 1) {
        int u = (t >= off) ? sh[t - off] : 0;
        __syncthreads();
        sh[t] += u;
        __syncthreads();
    }
    if (t < SCAN_BLKS) g_blockoff[t] = sh[t] - v;   // exclusive
}

__global__ void scan3_kernel() {
    __shared__ int sh[256];
    int t = threadIdx.x;
    int i = blockIdx.x * 256 + t;
    int v = (i < NN) ? g_deg[i] : 0;
    sh[t] = v;
    __syncthreads();
#pragma unroll
    for (int off = 1; off < 256; off <<= 1) {
        int u = (t >= off) ? sh[t - off] : 0;
        __syncthreads();
        sh[t] += u;
        __syncthreads();
    }
    if (i < NN) {
        int excl = g_blockoff[blockIdx.x] + sh[t] - v;
        g_csr[i]  = excl;
        g_fill[i] = excl;
    }
    if (i == 0) g_csr[NN] = EE;
}

// ---------------- scatter edge ids into CSR order ----------------
__global__ void scatter_kernel() {
    int e = blockIdx.x * blockDim.x + threadIdx.x;
    if (e >= EE) return;
    int pos = atomicAdd(&g_fill[g_edst[e]], 1);
    g_eid[pos] = e;
}

// ---------------- pre-convert A and W to tf32 bit patterns ----------------
__global__ void cvt_tf32_kernel(const float* __restrict__ A, const float* __restrict__ W) {
    const int NA4 = NN * IND / 4;      // 12.8M
    const int NW4 = IND * HIDD / 4;    // 204.8K
    int stride = gridDim.x * blockDim.x;
    for (int i = blockIdx.x * blockDim.x + threadIdx.x; i < NA4; i += stride) {
        float4 v = *(const float4*)(A + (size_t)i * 4);
        uint4 o = make_uint4(f2tf32(v.x), f2tf32(v.y), f2tf32(v.z), f2tf32(v.w));
        *(uint4*)(g_Atf + (size_t)i * 4) = o;
    }
    for (int i = blockIdx.x * blockDim.x + threadIdx.x; i < NW4; i += stride) {
        float4 v = *(const float4*)(W + (size_t)i * 4);
        uint4 o = make_uint4(f2tf32(v.x), f2tf32(v.y), f2tf32(v.z), f2tf32(v.w));
        *(uint4*)(g_Wtf + (size_t)i * 4) = o;
    }
}

// ---------------- stage prefetch: gmem -> smem via cp.async ----------------
__device__ __forceinline__ void prefetch_stage(int bm, int bn, int k0,
                                               uint32_t sA, uint32_t sB, int tid) {
#pragma unroll
    for (int i = 0; i < 4; i++) {
        int cid = tid + i * 256;
        int row = cid >> 3, kc = cid & 7;
        int g = bm + row; g = g < NN ? g : NN - 1;
        const float* src = g_Atf + (size_t)g * IND + k0 + kc * 4;
        uint32_t dst = sA + (uint32_t)(row * ASTR + kc * 4) * 4u;
        CP_ASYNC16(dst, src);
    }
#pragma unroll
    for (int i = 0; i < 5; i++) {
        int cid = tid + i * 256;
        int row = cid / 40, nc = cid % 40;
        const float* src = g_Wtf + (size_t)(k0 + row) * HIDD + bn + nc * 4;
        uint32_t dst = sB + (uint32_t)(row * BSTR + nc * 4) * 4u;
        CP_ASYNC16(dst, src);
    }
}

// ---------------- TF32 mma.sync GEMM: g_h = A_tf32 @ W_tf32 ----------------
__global__ void __launch_bounds__(256, 2) mma_gemm_kernel() {
    extern __shared__ float smf[];
    uint32_t sbase = smem_u32(smf);
    int tid = threadIdx.x, lane = tid & 31, w = tid >> 5;
    int bm = blockIdx.y * BM;
    int bn = blockIdx.x * BN;

    uint32_t sA[2] = { sbase, sbase + (uint32_t)(A_WORDS + B_WORDS) * 4u };
    uint32_t sB[2] = { sbase + (uint32_t)A_WORDS * 4u,
                       sbase + (uint32_t)(2 * A_WORDS + B_WORDS) * 4u };
    const uint32_t* fA[2] = { (const uint32_t*)smf,
                              (const uint32_t*)(smf + A_WORDS + B_WORDS) };
    const uint32_t* fB[2] = { (const uint32_t*)(smf + A_WORDS),
                              (const uint32_t*)(smf + 2 * A_WORDS + B_WORDS) };

    int wm = (w & 1) * 64;    // 2 warps along M
    int wn = (w >> 1) * 40;   // 4 warps along N
    int g4 = lane >> 2, t4 = lane & 3;

    float acc[4][5][4];
#pragma unroll
    for (int mt = 0; mt < 4; mt++)
#pragma unroll
        for (int nt = 0; nt < 5; nt++)
#pragma unroll
            for (int q = 0; q < 4; q++) acc[mt][nt][q] = 0.0f;

    prefetch_stage(bm, bn, 0, sA[0], sB[0], tid);
    CP_COMMIT();

    for (int s = 0; s < NSTG; s++) {
        int b = s & 1;
        if (s + 1 < NSTG) {
            prefetch_stage(bm, bn, (s + 1) * BKK, sA[1 - b], sB[1 - b], tid);
            CP_COMMIT();
            CP_WAIT(1);
        } else {
            CP_WAIT(0);
        }
        __syncthreads();

        const uint32_t* as = fA[b];
        const uint32_t* bs = fB[b];
#pragma unroll
        for (int ks = 0; ks < 4; ks++) {
            uint32_t af[4][4], bf[5][2];
            int kk = ks * 8 + t4;
#pragma unroll
            for (int mt = 0; mt < 4; mt++) {
                int r = wm + mt * 16 + g4;
                af[mt][0] = as[r * ASTR + kk];
                af[mt][1] = as[(r + 8) * ASTR + kk];
                af[mt][2] = as[r * ASTR + kk + 4];
                af[mt][3] = as[(r + 8) * ASTR + kk + 4];
            }
#pragma unroll
            for (int nt = 0; nt < 5; nt++) {
                int col = wn + nt * 8 + g4;
                bf[nt][0] = bs[kk * BSTR + col];
                bf[nt][1] = bs[(kk + 4) * BSTR + col];
            }
#pragma unroll
            for (int mt = 0; mt < 4; mt++)
#pragma unroll
                for (int nt = 0; nt < 5; nt++)
                    mma_tf32(acc[mt][nt], af[mt], bf[nt]);
        }
        __syncthreads();
    }

#pragma unroll
    for (int mt = 0; mt < 4; mt++) {
        int m0 = bm + wm + mt * 16 + g4;
#pragma unroll
        for (int nt = 0; nt < 5; nt++) {
            int n0 = bn + wn + nt * 8 + 2 * t4;
            if (m0 < NN)
                *(float2*)(g_h + (size_t)m0 * HIDD + n0) =
                    make_float2(acc[mt][nt][0], acc[mt][nt][1]);
            if (m0 + 8 < NN)
                *(float2*)(g_h + (size_t)(m0 + 8) * HIDD + n0) =
                    make_float2(acc[mt][nt][2], acc[mt][nt][3]);
        }
    }
}

// ---------------- per-node attention scores: warp per node ----------------
__global__ void node_scores_kernel(const float* __restrict__ a_src,
                                   const float* __restrict__ a_dst) {
    int warp = (blockIdx.x * blockDim.x + threadIdx.x) >> 5;
    int lane = threadIdx.x & 31;
    if (warp >= NN) return;
    const float* hrow = g_h + (size_t)warp * HIDD;
#pragma unroll
    for (int head = 0; head < NH; head++) {
        float ss = 0.f, dd = 0.f;
        for (int d = lane; d < OD; d += 32) {
            float hv = hrow[head * OD + d];
            ss = fmaf(hv, a_src[head * OD + d], ss);
            dd = fmaf(hv, a_dst[head * OD + d], dd);
        }
#pragma unroll
        for (int off = 16; off; off >>= 1) {
            ss += __shfl_xor_sync(0xffffffffu, ss, off);
            dd += __shfl_xor_sync(0xffffffffu, dd, off);
        }
        if (lane == 0) {
            g_sscore[warp * NH + head] = ss;
            g_dscore[warp * NH + head] = dd;
        }
    }
}

// ---------------- relation scores ----------------
__global__ void rel_scores_kernel(const float* __restrict__ rel_feat,
                                  const float* __restrict__ a_rel) {
    int t = threadIdx.x;
    if (t >= NR * NH) return;
    int r = t >> 2, hh = t & 3;
    float acc = 0.f;
    for (int d = 0; d < OD; d++)
        acc = fmaf(rel_feat[r * HIDD + hh * OD + d], a_rel[hh * OD + d], acc);
    g_relscore[t] = acc;
}

// ---------------- edge logits + leaky relu + segment max ----------------
__global__ void logits_kernel() {
    int t = blockIdx.x * blockDim.x + threadIdx.x;
    if (t >= EE * NH) return;
    int e = t >> 2, hh = t & 3;
    int s = g_esrc[e], d = g_edst[e], ty = g_etype[e];
    float l = g_sscore[s * NH + hh] + g_dscore[d * NH + hh] + g_relscore[ty * NH + hh];
    l = (l > 0.f) ? l : 0.2f * l;
    g_logits[t] = l;
    atomicMax(&g_segmax[d * NH + hh], enc_f2i(l));
}

// ---------------- exp + segment sum ----------------
__global__ void expsum_kernel() {
    int t = blockIdx.x * blockDim.x + threadIdx.x;
    if (t >= EE * NH) return;
    int e = t >> 2, hh = t & 3;
    int d = g_edst[e];
    float mx = dec_i2f(g_segmax[d * NH + hh]);
    float ev = __expf(g_logits[t] - mx);
    g_eexp[t] = ev;
    atomicAdd(&g_denom[d * NH + hh], ev);
}

// ---------------- CSR gather aggregate, needed dsts only ----------------
__global__ void __launch_bounds__(224) aggregate_csr_kernel() {
    int dst = blockIdx.x;
    if (!g_need[dst]) return;              // ~71% of blocks exit immediately
    int t = threadIdx.x;
    if (t >= 200) return;
    int head = t / 50;
    int beg = g_csr[dst], end = g_csr[dst + 1];
    float inv_den = (beg < end) ? __frcp_rn(g_denom[dst * NH + head]) : 0.0f;
    float4 acc = make_float4(0.f, 0.f, 0.f, 0.f);
    for (int p = beg; p < end; p++) {
        int e = g_eid[p];
        float a = g_eexp[e * NH + head] * inv_den;
        int src = g_esrc[e];
        float4 hv = *(const float4*)(g_h + (size_t)src * HIDD + t * 4);
        acc.x = fmaf(a, hv.x, acc.x);
        acc.y = fmaf(a, hv.y, acc.y);
        acc.z = fmaf(a, hv.z, acc.z);
        acc.w = fmaf(a, hv.w, acc.w);
    }
    *(float4*)(g_out + (size_t)dst * HIDD + t * 4) = acc;
}

// ---------------- DistMult scoring: warp per triple ----------------
__global__ void score_kernel(const float* __restrict__ bias,
                             const float* __restrict__ rel_emb,
                             float* __restrict__ out) {
    int warp = (blockIdx.x * blockDim.x + threadIdx.x) >> 5;
    int lane = threadIdx.x & 31;
    if (warp >= BB) return;
    int s = g_sid[warp], r = g_rid[warp], d = g_did[warp];
    const float* sv = g_out + (size_t)s * HIDD;
    const float* dv = g_out + (size_t)d * HIDD;
    const float* rv = rel_emb + (size_t)r * HIDD;
    float acc = 0.f;
    for (int j = lane; j < HIDD; j += 32)
        acc = fmaf((sv[j] + bias[j]) * rv[j], (dv[j] + bias[j]), acc);
#pragma unroll
    for (int off = 16; off; off >>= 1) acc += __shfl_xor_sync(0xffffffffu, acc, off);
    if (lane == 0) out[warp] = acc;
}

// ---------------- launch ----------------
extern "C" void kernel_launch(void* const* d_in, const int* in_sizes, int n_in,
                              void* d_out, int out_size) {
    const float* node_emb  = (const float*)d_in[0];
    const float* W         = (const float*)d_in[1];
    const float* bias      = (const float*)d_in[2];
    const float* a_src     = (const float*)d_in[3];
    const float* a_dst     = (const float*)d_in[4];
    const float* a_rel     = (const float*)d_in[5];
    const float* rel_feat  = (const float*)d_in[6];
    const float* rel_emb   = (const float*)d_in[7];
    const void*  edge_index = d_in[8];
    const void*  edge_type  = d_in[9];
    const void*  src_ids    = d_in[10];
    const void*  rel_ids    = d_in[11];
    const void*  dst_ids    = d_in[12];
    float* out = (float*)d_out;

    static bool attr_set = false;
    if (!attr_set) {
        cudaFuncSetAttribute(mma_gemm_kernel,
                             cudaFuncAttributeMaxDynamicSharedMemorySize,
                             SMEM_WORDS * 4);
        attr_set = true;
    }

    init_kernel<<<(NN * NH + 255) / 256, 256>>>();
    detect_kernel<<<(EE + 255) / 256, 256>>>(edge_index);
    convert_kernel<<<(EE + 255) / 256, 256>>>(edge_index, edge_type, src_ids, rel_ids, dst_ids);
    scan1_kernel<<<SCAN_BLKS, 256>>>();
    scan2_kernel<<<1, 256>>>();
    scan3_kernel<<<SCAN_BLKS, 256>>>();
    scatter_kernel<<<(EE + 255) / 256, 256>>>();

    cvt_tf32_kernel<<<8192, 256>>>(node_emb, W);

    dim3 ggrid(HIDD / BN, (NN + BM - 1) / BM);   // (5, 391)
    mma_gemm_kernel<<<ggrid, 256, SMEM_WORDS * 4>>>();

    node_scores_kernel<<<(NN * 32 + 255) / 256, 256>>>(a_src, a_dst);
    rel_scores_kernel<<<1, 256>>>(rel_feat, a_rel);
    logits_kernel<<<(EE * NH + 255) / 256, 256>>>();
    expsum_kernel<<<(EE * NH + 255) / 256, 256>>>();
    aggregate_csr_kernel<<<NN, 224>>>();
    score_kernel<<<(BB * 32 + 255) / 256, 256>>>(bias, rel_emb, out);
}

// round 12
// speedup vs baseline: 2.6003x; 1.4360x over previous
#include <cuda_runtime.h>
#include <cstdint>
#include <cstddef>

#define NN   50000
#define IND  1024
#define EE   100000
#define NR   40
#define NH   4
#define OD   200
#define HIDD 800
#define BB   8192

// ---- GEMM tiling (mma.sync tf32, sm_80-class features only) ----
#define BM   128
#define BN   160
#define BKK  32
#define NSTG (IND / BKK)        // 32
#define APAD 4
#define BPAD 8
#define ASTR (BKK + APAD)       // 36 words, conflict-free a-frag banks
#define BSTR (BN + BPAD)        // 168 words, conflict-free b-frag banks
#define A_WORDS (BM * ASTR)     // 4608
#define B_WORDS (BKK * BSTR)    // 5376
#define SMEM_WORDS (2 * (A_WORDS + B_WORDS))   // 19968 words = 79872 B

#define SCAN_BLKS ((NN + 255) / 256)           // 196

// ---------------- scratch (static device allocations, allowed) ----------------
static __device__ float g_h[(size_t)NN * HIDD];     // node features (computed rows only)
static __device__ float g_out[(size_t)NN * HIDD];   // aggregated output (needed rows only)
static __device__ float g_Atf[(size_t)NN * IND];    // tf32 pre-converted A (needed rows)
static __device__ float g_Wtf[(size_t)IND * HIDD];  // tf32 pre-converted W       (3.3 MB)
static __device__ float g_sscore[NN * NH];
static __device__ float g_dscore[NN * NH];
static __device__ float g_relscore[NR * NH];
static __device__ float g_logits[EE * NH];
static __device__ float g_eexp[EE * NH];            // exp(logit - segmax)
static __device__ int   g_segmax[NN * NH];
static __device__ float g_denom[NN * NH];
static __device__ int   g_esrc[EE];
static __device__ int   g_edst[EE];
static __device__ int   g_etype[EE];
static __device__ int   g_deg[NN];
static __device__ int   g_need[NN];     // node referenced by src_ids/dst_ids
static __device__ int   g_hneed[NN];    // h row must be computed
static __device__ int   g_rowlist[NN];  // compacted list of hneed rows
static __device__ int   g_nrows;        // number of compacted rows
static __device__ int   g_blocksum[SCAN_BLKS];
static __device__ int   g_blockoff[SCAN_BLKS];
static __device__ int   g_rbsum[SCAN_BLKS];
static __device__ int   g_rboff[SCAN_BLKS];
static __device__ int   g_csr[NN + 1];
static __device__ int   g_fill[NN];
static __device__ int   g_eid[EE];
static __device__ int   g_sid[BB];
static __device__ int   g_rid[BB];
static __device__ int   g_did[BB];
static __device__ int   g_not64;   // 1 if index buffers are int32

// ---------------- helpers ----------------
__device__ __forceinline__ uint32_t smem_u32(const void* p) {
    uint32_t a;
    asm("{ .reg .u64 t; cvta.to.shared.u64 t, %1; cvt.u32.u64 %0, t; }" : "=r"(a) : "l"(p));
    return a;
}
__device__ __forceinline__ uint32_t f2tf32(float f) {
    uint32_t r;
    asm("cvt.rna.tf32.f32 %0, %1;" : "=r"(r) : "f"(f));
    return r;
}
__device__ __forceinline__ void mma_tf32(float* c, const uint32_t* a, const uint32_t* b) {
    asm volatile(
        "mma.sync.aligned.m16n8k8.row.col.f32.tf32.tf32.f32 "
        "{%0,%1,%2,%3}, {%4,%5,%6,%7}, {%8,%9}, {%0,%1,%2,%3};"
        : "+f"(c[0]), "+f"(c[1]), "+f"(c[2]), "+f"(c[3])
        : "r"(a[0]), "r"(a[1]), "r"(a[2]), "r"(a[3]), "r"(b[0]), "r"(b[1]));
}
#define CP_ASYNC16(dst, src) \
    asm volatile("cp.async.cg.shared.global [%0], [%1], 16;" :: "r"(dst), "l"(src))
#define CP_COMMIT()  asm volatile("cp.async.commit_group;" ::: "memory")
#define CP_WAIT(n)   asm volatile("cp.async.wait_group %0;" :: "n"(n) : "memory")

__device__ __forceinline__ int enc_f2i(float f) {
    int i = __float_as_int(f);
    return i >= 0 ? i : (i ^ 0x7fffffff);
}
__device__ __forceinline__ float dec_i2f(int k) {
    return __int_as_float(k >= 0 ? k : (k ^ 0x7fffffff));
}
__device__ __forceinline__ int fetch_idx(const void* p, long long i, int is64) {
    return is64 ? (int)((const long long*)p)[i] : ((const int*)p)[i];
}

// ---------------- init ----------------
__global__ void init_kernel() {
    int i = blockIdx.x * blockDim.x + threadIdx.x;
    if (i < NN * NH) { g_segmax[i] = INT_MIN; g_denom[i] = 0.0f; }
    if (i < NN) { g_deg[i] = 0; g_need[i] = 0; g_hneed[i] = 0; }
    if (i == 0) g_not64 = 0;
}

// ---------------- dtype detection ----------------
__global__ void detect_kernel(const void* edge_index) {
    int i = blockIdx.x * blockDim.x + threadIdx.x;
    if (i < EE) {
        int w = ((const int*)edge_index)[2 * i + 1];
        if (w != 0) g_not64 = 1;
    }
}

// ---------------- convert index arrays to int32 + degree histogram + need flags ----------------
__global__ void convert_kernel(const void* edge_index, const void* edge_type,
                               const void* src_ids, const void* rel_ids, const void* dst_ids) {
    int is64 = (g_not64 == 0);
    int i = blockIdx.x * blockDim.x + threadIdx.x;
    if (i < EE) {
        int s = fetch_idx(edge_index, i, is64);
        int d = fetch_idx(edge_index, (long long)EE + i, is64);
        g_esrc[i]  = s;
        g_edst[i]  = d;
        g_etype[i] = fetch_idx(edge_type, i, is64);
        atomicAdd(&g_deg[d], 1);
    }
    if (i < BB) {
        int s = fetch_idx(src_ids, i, is64);
        int d = fetch_idx(dst_ids, i, is64);
        g_sid[i] = s;
        g_rid[i] = fetch_idx(rel_ids, i, is64);
        g_did[i] = d;
        g_need[s] = 1;       // benign races: all write 1
        g_need[d] = 1;
    }
}

// ---------------- mark h rows that must be computed ----------------
__global__ void hmark_kernel() {
    int i = blockIdx.x * blockDim.x + threadIdx.x;
    if (i < EE) {
        if (g_need[g_edst[i]]) g_hneed[g_esrc[i]] = 1;  // s_score + h[src] gather
    }
    if (i < NN) {
        if (g_need[i]) g_hneed[i] = 1;                  // d_score for needed dsts
    }
}

// ---------------- parallel 3-phase exclusive scan of degrees ----------------
__global__ void scan1_kernel() {
    __shared__ int sh[256];
    int t = threadIdx.x;
    int i = blockIdx.x * 256 + t;
    sh[t] = (i < NN) ? g_deg[i] : 0;
    __syncthreads();
#pragma unroll
    for (int off = 128; off; off >>= 1) {
        if (t < off) sh[t] += sh[t + off];
        __syncthreads();
    }
    if (t == 0) g_blocksum[blockIdx.x] = sh[0];
}

__global__ void scan2_kernel() {
    __shared__ int sh[256];
    int t = threadIdx.x;
    int v = (t < SCAN_BLKS) ? g_blocksum[t] : 0;
    sh[t] = v;
    __syncthreads();
#pragma unroll
    for (int off = 1; off < 256; off <<= 1) {
        int u = (t >= off) ? sh[t - off] : 0;
        __syncthreads();
        sh[t] += u;
        __syncthreads();
    }
    if (t < SCAN_BLKS) g_blockoff[t] = sh[t] - v;   // exclusive
}

__global__ void scan3_kernel() {
    __shared__ int sh[256];
    int t = threadIdx.x;
    int i = blockIdx.x * 256 + t;
    int v = (i < NN) ? g_deg[i] : 0;
    sh[t] = v;
    __syncthreads();
#pragma unroll
    for (int off = 1; off < 256; off <<= 1) {
        int u = (t >= off) ? sh[t - off] : 0;
        __syncthreads();
        sh[t] += u;
        __syncthreads();
    }
    if (i < NN) {
        int excl = g_blockoff[blockIdx.x] + sh[t] - v;
        g_csr[i]  = excl;
        g_fill[i] = excl;
    }
    if (i == 0) g_csr[NN] = EE;
}

// ---------------- row compaction scan (same 3-phase pattern over g_hneed) ----------------
__global__ void rowscan1_kernel() {
    __shared__ int sh[256];
    int t = threadIdx.x;
    int i = blockIdx.x * 256 + t;
    sh[t] = (i < NN) ? g_hneed[i] : 0;
    __syncthreads();
#pragma unroll
    for (int off = 128; off; off >>= 1) {
        if (t < off) sh[t] += sh[t + off];
        __syncthreads();
    }
    if (t == 0) g_rbsum[blockIdx.x] = sh[0];
}

__global__ void rowscan2_kernel() {
    __shared__ int sh[256];
    int t = threadIdx.x;
    int v = (t < SCAN_BLKS) ? g_rbsum[t] : 0;
    sh[t] = v;
    __syncthreads();
#pragma unroll
    for (int off = 1; off < 256; off <<= 1) {
        int u = (t >= off) ? sh[t - off] : 0;
        __syncthreads();
        sh[t] += u;
        __syncthreads();
    }
    if (t < SCAN_BLKS) g_rboff[t] = sh[t] - v;   // exclusive
    if (t == SCAN_BLKS - 1) g_nrows = sh[t];     // total
}

__global__ void rowscan3_kernel() {
    __shared__ int sh[256];
    int t = threadIdx.x;
    int i = blockIdx.x * 256 + t;
    int v = (i < NN) ? g_hneed[i] : 0;
    sh[t] = v;
    __syncthreads();
#pragma unroll
    for (int off = 1; off < 256; off <<= 1) {
        int u = (t >= off) ? sh[t - off] : 0;
        __syncthreads();
        sh[t] += u;
        __syncthreads();
    }
    if (i < NN && v) {
        int pos = g_rboff[blockIdx.x] + sh[t] - v;
        g_rowlist[pos] = i;
    }
}

// ---------------- scatter edge ids into CSR order ----------------
__global__ void scatter_kernel() {
    int e = blockIdx.x * blockDim.x + threadIdx.x;
    if (e >= EE) return;
    int pos = atomicAdd(&g_fill[g_edst[e]], 1);
    g_eid[pos] = e;
}

// ---------------- pre-convert A (needed rows only) and W to tf32 ----------------
__global__ void cvt_tf32_kernel(const float* __restrict__ A, const float* __restrict__ W) {
    const int NA4 = NN * IND / 4;      // 12.8M float4s, 256 per row
    const int NW4 = IND * HIDD / 4;    // 204.8K
    int stride = gridDim.x * blockDim.x;
    for (int i = blockIdx.x * blockDim.x + threadIdx.x; i < NA4; i += stride) {
        int row = i >> 8;              // i / (IND/4)
        if (!g_hneed[row]) continue;
        float4 v = *(const float4*)(A + (size_t)i * 4);
        uint4 o = make_uint4(f2tf32(v.x), f2tf32(v.y), f2tf32(v.z), f2tf32(v.w));
        *(uint4*)(g_Atf + (size_t)i * 4) = o;
    }
    for (int i = blockIdx.x * blockDim.x + threadIdx.x; i < NW4; i += stride) {
        float4 v = *(const float4*)(W + (size_t)i * 4);
        uint4 o = make_uint4(f2tf32(v.x), f2tf32(v.y), f2tf32(v.z), f2tf32(v.w));
        *(uint4*)(g_Wtf + (size_t)i * 4) = o;
    }
}

// ---------------- stage prefetch: gmem -> smem via cp.async (A rows via rowlist) ----------------
__device__ __forceinline__ void prefetch_stage(const int* grow, int bn, int k0,
                                               uint32_t sA, uint32_t sB, int tid) {
#pragma unroll
    for (int i = 0; i < 4; i++) {
        int cid = tid + i * 256;
        int row = cid >> 3, kc = cid & 7;
        const float* src = g_Atf + (size_t)grow[i] * IND + k0 + kc * 4;
        uint32_t dst = sA + (uint32_t)(row * ASTR + kc * 4) * 4u;
        CP_ASYNC16(dst, src);
    }
#pragma unroll
    for (int i = 0; i < 5; i++) {
        int cid = tid + i * 256;
        int row = cid / 40, nc = cid % 40;
        const float* src = g_Wtf + (size_t)(k0 + row) * HIDD + bn + nc * 4;
        uint32_t dst = sB + (uint32_t)(row * BSTR + nc * 4) * 4u;
        CP_ASYNC16(dst, src);
    }
}

// ---------------- TF32 mma.sync GEMM over compacted rows ----------------
__global__ void __launch_bounds__(256, 2) mma_gemm_kernel() {
    int nrows = g_nrows;
    int bm = blockIdx.y * BM;
    if (bm >= nrows) return;                // uniform early exit, before any barrier

    extern __shared__ float smf[];
    uint32_t sbase = smem_u32(smf);
    int tid = threadIdx.x, lane = tid & 31, w = tid >> 5;
    int bn = blockIdx.x * BN;

    // loop-invariant gather indices for this thread's 4 A-chunks (outside MMA loop)
    int grow[4];
#pragma unroll
    for (int i = 0; i < 4; i++) {
        int ridx = bm + ((tid + i * 256) >> 3);
        grow[i] = g_rowlist[ridx < nrows ? ridx : nrows - 1];
    }

    uint32_t sA[2] = { sbase, sbase + (uint32_t)(A_WORDS + B_WORDS) * 4u };
    uint32_t sB[2] = { sbase + (uint32_t)A_WORDS * 4u,
                       sbase + (uint32_t)(2 * A_WORDS + B_WORDS) * 4u };
    const uint32_t* fA[2] = { (const uint32_t*)smf,
                              (const uint32_t*)(smf + A_WORDS + B_WORDS) };
    const uint32_t* fB[2] = { (const uint32_t*)(smf + A_WORDS),
                              (const uint32_t*)(smf + 2 * A_WORDS + B_WORDS) };

    int wm = (w & 1) * 64;    // 2 warps along M
    int wn = (w >> 1) * 40;   // 4 warps along N
    int g4 = lane >> 2, t4 = lane & 3;

    float acc[4][5][4];
#pragma unroll
    for (int mt = 0; mt < 4; mt++)
#pragma unroll
        for (int nt = 0; nt < 5; nt++)
#pragma unroll
            for (int q = 0; q < 4; q++) acc[mt][nt][q] = 0.0f;

    prefetch_stage(grow, bn, 0, sA[0], sB[0], tid);
    CP_COMMIT();

    for (int s = 0; s < NSTG; s++) {
        int b = s & 1;
        if (s + 1 < NSTG) {
            prefetch_stage(grow, bn, (s + 1) * BKK, sA[1 - b], sB[1 - b], tid);
            CP_COMMIT();
            CP_WAIT(1);
        } else {
            CP_WAIT(0);
        }
        __syncthreads();

        const uint32_t* as = fA[b];
        const uint32_t* bs = fB[b];
#pragma unroll
        for (int ks = 0; ks < 4; ks++) {
            uint32_t af[4][4], bf[5][2];
            int kk = ks * 8 + t4;
#pragma unroll
            for (int mt = 0; mt < 4; mt++) {
                int r = wm + mt * 16 + g4;
                af[mt][0] = as[r * ASTR + kk];
                af[mt][1] = as[(r + 8) * ASTR + kk];
                af[mt][2] = as[r * ASTR + kk + 4];
                af[mt][3] = as[(r + 8) * ASTR + kk + 4];
            }
#pragma unroll
            for (int nt = 0; nt < 5; nt++) {
                int col = wn + nt * 8 + g4;
                bf[nt][0] = bs[kk * BSTR + col];
                bf[nt][1] = bs[(kk + 4) * BSTR + col];
            }
#pragma unroll
            for (int mt = 0; mt < 4; mt++)
#pragma unroll
                for (int nt = 0; nt < 5; nt++)
                    mma_tf32(acc[mt][nt], af[mt], bf[nt]);
        }
        __syncthreads();
    }

    // epilogue: scatter rows back through rowlist
#pragma unroll
    for (int mt = 0; mt < 4; mt++) {
        int ridx = bm + wm + mt * 16 + g4;
        int row0 = (ridx < nrows) ? g_rowlist[ridx] : -1;
        int row1 = (ridx + 8 < nrows) ? g_rowlist[ridx + 8] : -1;
#pragma unroll
        for (int nt = 0; nt < 5; nt++) {
            int n0 = bn + wn + nt * 8 + 2 * t4;
            if (row0 >= 0)
                *(float2*)(g_h + (size_t)row0 * HIDD + n0) =
                    make_float2(acc[mt][nt][0], acc[mt][nt][1]);
            if (row1 >= 0)
                *(float2*)(g_h + (size_t)row1 * HIDD + n0) =
                    make_float2(acc[mt][nt][2], acc[mt][nt][3]);
        }
    }
}

// ---------------- per-node attention scores: warp per compacted row ----------------
__global__ void node_scores_kernel(const float* __restrict__ a_src,
                                   const float* __restrict__ a_dst) {
    int i = (blockIdx.x * blockDim.x + threadIdx.x) >> 5;
    int lane = threadIdx.x & 31;
    if (i >= g_nrows) return;
    int node = g_rowlist[i];
    const float* hrow = g_h + (size_t)node * HIDD;
#pragma unroll
    for (int head = 0; head < NH; head++) {
        float ss = 0.f, dd = 0.f;
        for (int d = lane; d < OD; d += 32) {
            float hv = hrow[head * OD + d];
            ss = fmaf(hv, a_src[head * OD + d], ss);
            dd = fmaf(hv, a_dst[head * OD + d], dd);
        }
#pragma unroll
        for (int off = 16; off; off >>= 1) {
            ss += __shfl_xor_sync(0xffffffffu, ss, off);
            dd += __shfl_xor_sync(0xffffffffu, dd, off);
        }
        if (lane == 0) {
            g_sscore[node * NH + head] = ss;
            g_dscore[node * NH + head] = dd;
        }
    }
}

// ---------------- relation scores ----------------
__global__ void rel_scores_kernel(const float* __restrict__ rel_feat,
                                  const float* __restrict__ a_rel) {
    int t = threadIdx.x;
    if (t >= NR * NH) return;
    int r = t >> 2, hh = t & 3;
    float acc = 0.f;
    for (int d = 0; d < OD; d++)
        acc = fmaf(rel_feat[r * HIDD + hh * OD + d], a_rel[hh * OD + d], acc);
    g_relscore[t] = acc;
}

// ---------------- edge logits + leaky relu + segment max (needed dsts only) ----------------
__global__ void logits_kernel() {
    int t = blockIdx.x * blockDim.x + threadIdx.x;
    if (t >= EE * NH) return;
    int e = t >> 2, hh = t & 3;
    int d = g_edst[e];
    if (!g_need[d]) return;                // softmax of unneeded dst never read
    int s = g_esrc[e], ty = g_etype[e];
    float l = g_sscore[s * NH + hh] + g_dscore[d * NH + hh] + g_relscore[ty * NH + hh];
    l = (l > 0.f) ? l : 0.2f * l;
    g_logits[t] = l;
    atomicMax(&g_segmax[d * NH + hh], enc_f2i(l));
}

// ---------------- exp + segment sum (needed dsts only) ----------------
__global__ void expsum_kernel() {
    int t = blockIdx.x * blockDim.x + threadIdx.x;
    if (t >= EE * NH) return;
    int e = t >> 2, hh = t & 3;
    int d = g_edst[e];
    if (!g_need[d]) return;
    float mx = dec_i2f(g_segmax[d * NH + hh]);
    float ev = __expf(g_logits[t] - mx);
    g_eexp[t] = ev;
    atomicAdd(&g_denom[d * NH + hh], ev);
}

// ---------------- CSR gather aggregate, needed dsts only ----------------
__global__ void __launch_bounds__(224) aggregate_csr_kernel() {
    int dst = blockIdx.x;
    if (!g_need[dst]) return;              // ~72% of blocks exit immediately
    int t = threadIdx.x;
    if (t >= 200) return;
    int head = t / 50;
    int beg = g_csr[dst], end = g_csr[dst + 1];
    float inv_den = (beg < end) ? __frcp_rn(g_denom[dst * NH + head]) : 0.0f;
    float4 acc = make_float4(0.f, 0.f, 0.f, 0.f);
    for (int p = beg; p < end; p++) {
        int e = g_eid[p];
        float a = g_eexp[e * NH + head] * inv_den;
        int src = g_esrc[e];
        float4 hv = *(const float4*)(g_h + (size_t)src * HIDD + t * 4);
        acc.x = fmaf(a, hv.x, acc.x);
        acc.y = fmaf(a, hv.y, acc.y);
        acc.z = fmaf(a, hv.z, acc.z);
        acc.w = fmaf(a, hv.w, acc.w);
    }
    *(float4*)(g_out + (size_t)dst * HIDD + t * 4) = acc;
}

// ---------------- DistMult scoring: warp per triple ----------------
__global__ void score_kernel(const float* __restrict__ bias,
                             const float* __restrict__ rel_emb,
                             float* __restrict__ out) {
    int warp = (blockIdx.x * blockDim.x + threadIdx.x) >> 5;
    int lane = threadIdx.x & 31;
    if (warp >= BB) return;
    int s = g_sid[warp], r = g_rid[warp], d = g_did[warp];
    const float* sv = g_out + (size_t)s * HIDD;
    const float* dv = g_out + (size_t)d * HIDD;
    const float* rv = rel_emb + (size_t)r * HIDD;
    float acc = 0.f;
    for (int j = lane; j < HIDD; j += 32)
        acc = fmaf((sv[j] + bias[j]) * rv[j], (dv[j] + bias[j]), acc);
#pragma unroll
    for (int off = 16; off; off >>= 1) acc += __shfl_xor_sync(0xffffffffu, acc, off);
    if (lane == 0) out[warp] = acc;
}

// ---------------- launch ----------------
extern "C" void kernel_launch(void* const* d_in, const int* in_sizes, int n_in,
                              void* d_out, int out_size) {
    const float* node_emb  = (const float*)d_in[0];
    const float* W         = (const float*)d_in[1];
    const float* bias      = (const float*)d_in[2];
    const float* a_src     = (const float*)d_in[3];
    const float* a_dst     = (const float*)d_in[4];
    const float* a_rel     = (const float*)d_in[5];
    const float* rel_feat  = (const float*)d_in[6];
    const float* rel_emb   = (const float*)d_in[7];
    const void*  edge_index = d_in[8];
    const void*  edge_type  = d_in[9];
    const void*  src_ids    = d_in[10];
    const void*  rel_ids    = d_in[11];
    const void*  dst_ids    = d_in[12];
    float* out = (float*)d_out;

    static bool attr_set = false;
    if (!attr_set) {
        cudaFuncSetAttribute(mma_gemm_kernel,
                             cudaFuncAttributeMaxDynamicSharedMemorySize,
                             SMEM_WORDS * 4);
        attr_set = true;
    }

    init_kernel<<<(NN * NH + 255) / 256, 256>>>();
    detect_kernel<<<(EE + 255) / 256, 256>>>(edge_index);
    convert_kernel<<<(EE + 255) / 256, 256>>>(edge_index, edge_type, src_ids, rel_ids, dst_ids);
    hmark_kernel<<<(EE + 255) / 256, 256>>>();
    scan1_kernel<<<SCAN_BLKS, 256>>>();
    scan2_kernel<<<1, 256>>>();
    scan3_kernel<<<SCAN_BLKS, 256>>>();
    rowscan1_kernel<<<SCAN_BLKS, 256>>>();
    rowscan2_kernel<<<1, 256>>>();
    rowscan3_kernel<<<SCAN_BLKS, 256>>>();
    scatter_kernel<<<(EE + 255) / 256, 256>>>();

    cvt_tf32_kernel<<<8192, 256>>>(node_emb, W);

    dim3 ggrid(HIDD / BN, (NN + BM - 1) / BM);   // (5, 391); CTAs past g_nrows exit
    mma_gemm_kernel<<<ggrid, 256, SMEM_WORDS * 4>>>();

    node_scores_kernel<<<(NN * 32 + 255) / 256, 256>>>(a_src, a_dst);
    rel_scores_kernel<<<1, 256>>>(rel_feat, a_rel);
    logits_kernel<<<(EE * NH + 255) / 256, 256>>>();
    expsum_kernel<<<(EE * NH + 255) / 256, 256>>>();
    aggregate_csr_kernel<<<NN, 224>>>();
    score_kernel<<<(BB * 32 + 255) / 256, 256>>>(bias, rel_emb, out);
}